// round 3
// baseline (speedup 1.0000x reference)
#include <cuda_runtime.h>
#include <cstdint>

#define TGT 2048
#define SRC 2048
#define BHN 16
#define DH  64
#define QK_SCALE 0.125f   // 1/sqrt(64)

// ---------------------------------------------------------------------------
// Kernel A: W[h,t,s] = mask[t,s] ? -1e8 : (1/8) * dot(Q[t,h,:], K[s,h,:])
// 128x128 output tile per block, D=64 fully resident in SMEM (transposed),
// 8x8 register tile per thread (split 4+4 rows/cols for conflict-free float4).
// Mask is int32 (bool widened by the harness).
// ---------------------------------------------------------------------------
__global__ __launch_bounds__(256, 2) void qk_logits_kernel(
    const float* __restrict__ Q, const float* __restrict__ K,
    const int* __restrict__ mask, float* __restrict__ W)
{
    extern __shared__ float sm[];
    float* sQT = sm;             // [64][132] (d-major, padded)
    float* sKT = sm + 64 * 132;  // [64][132]

    const int h   = blockIdx.z;
    const int tb  = blockIdx.y * 128;
    const int sb  = blockIdx.x * 128;
    const int tid = threadIdx.x;

    // Load + transpose Q and K tiles (each 128 rows x 64 floats).
#pragma unroll
    for (int k = 0; k < 8; ++k) {
        int i  = tid + k * 256;       // float4 index, 0..2047
        int r  = i >> 4;              // 0..127
        int d4 = (i & 15) << 2;       // 0..60
        float4 v = *reinterpret_cast<const float4*>(
            Q + (size_t)(tb + r) * (BHN * DH) + h * DH + d4);
        sQT[(d4 + 0) * 132 + r] = v.x * QK_SCALE;
        sQT[(d4 + 1) * 132 + r] = v.y * QK_SCALE;
        sQT[(d4 + 2) * 132 + r] = v.z * QK_SCALE;
        sQT[(d4 + 3) * 132 + r] = v.w * QK_SCALE;
        float4 u = *reinterpret_cast<const float4*>(
            K + (size_t)(sb + r) * (BHN * DH) + h * DH + d4);
        sKT[(d4 + 0) * 132 + r] = u.x;
        sKT[(d4 + 1) * 132 + r] = u.y;
        sKT[(d4 + 2) * 132 + r] = u.z;
        sKT[(d4 + 3) * 132 + r] = u.w;
    }
    __syncthreads();

    const int tx = tid & 15, ty = tid >> 4;
    const int r0 = ty * 4, r1 = r0 + 64;
    const int c0 = tx * 4, c1 = c0 + 64;

    float acc[8][8];
#pragma unroll
    for (int i = 0; i < 8; ++i)
#pragma unroll
        for (int j = 0; j < 8; ++j) acc[i][j] = 0.0f;

#pragma unroll 4
    for (int d = 0; d < 64; ++d) {
        const float* qrow = &sQT[d * 132];
        const float* krow = &sKT[d * 132];
        float4 qa = *reinterpret_cast<const float4*>(qrow + r0);
        float4 qb = *reinterpret_cast<const float4*>(qrow + r1);
        float4 ka = *reinterpret_cast<const float4*>(krow + c0);
        float4 kb = *reinterpret_cast<const float4*>(krow + c1);
        float qs[8] = {qa.x, qa.y, qa.z, qa.w, qb.x, qb.y, qb.z, qb.w};
        float ks[8] = {ka.x, ka.y, ka.z, ka.w, kb.x, kb.y, kb.z, kb.w};
#pragma unroll
        for (int i = 0; i < 8; ++i)
#pragma unroll
            for (int j = 0; j < 8; ++j) acc[i][j] += qs[i] * ks[j];
    }

    // Epilogue: apply mask (int32 booleans), write logits.
#pragma unroll
    for (int i = 0; i < 8; ++i) {
        int r = (i < 4) ? (r0 + i) : (r1 + i - 4);
        int t = tb + r;
        const int* mrow = mask + (size_t)t * SRC + sb;
        float* wrow = W + ((size_t)h * TGT + t) * SRC + sb;

        int4 m0 = *reinterpret_cast<const int4*>(mrow + c0);
        float4 o0;
        o0.x = m0.x ? -1e8f : acc[i][0];
        o0.y = m0.y ? -1e8f : acc[i][1];
        o0.z = m0.z ? -1e8f : acc[i][2];
        o0.w = m0.w ? -1e8f : acc[i][3];
        *reinterpret_cast<float4*>(wrow + c0) = o0;

        int4 m1 = *reinterpret_cast<const int4*>(mrow + c1);
        float4 o1;
        o1.x = m1.x ? -1e8f : acc[i][4];
        o1.y = m1.y ? -1e8f : acc[i][5];
        o1.z = m1.z ? -1e8f : acc[i][6];
        o1.w = m1.w ? -1e8f : acc[i][7];
        *reinterpret_cast<float4*>(wrow + c1) = o1;
    }
}

// ---------------------------------------------------------------------------
// Kernel B: in-place row softmax over W. One block (256 threads) per row of 2048.
// ---------------------------------------------------------------------------
__global__ __launch_bounds__(256) void softmax_kernel(float* __restrict__ W)
{
    __shared__ float smax[8];
    __shared__ float ssum[8];

    float* p = W + (size_t)blockIdx.x * SRC;
    const int tid = threadIdx.x;

    float4 a = *reinterpret_cast<const float4*>(p + tid * 4);
    float4 b = *reinterpret_cast<const float4*>(p + 1024 + tid * 4);

    float m = fmaxf(fmaxf(fmaxf(a.x, a.y), fmaxf(a.z, a.w)),
                    fmaxf(fmaxf(b.x, b.y), fmaxf(b.z, b.w)));
#pragma unroll
    for (int o = 16; o > 0; o >>= 1) m = fmaxf(m, __shfl_xor_sync(0xffffffffu, m, o));
    if ((tid & 31) == 0) smax[tid >> 5] = m;
    __syncthreads();
    float mx = smax[0];
#pragma unroll
    for (int i = 1; i < 8; ++i) mx = fmaxf(mx, smax[i]);

    a.x = __expf(a.x - mx); a.y = __expf(a.y - mx);
    a.z = __expf(a.z - mx); a.w = __expf(a.w - mx);
    b.x = __expf(b.x - mx); b.y = __expf(b.y - mx);
    b.z = __expf(b.z - mx); b.w = __expf(b.w - mx);

    float s = a.x + a.y + a.z + a.w + b.x + b.y + b.z + b.w;
#pragma unroll
    for (int o = 16; o > 0; o >>= 1) s += __shfl_xor_sync(0xffffffffu, s, o);
    if ((tid & 31) == 0) ssum[tid >> 5] = s;
    __syncthreads();
    float tot = 0.0f;
#pragma unroll
    for (int i = 0; i < 8; ++i) tot += ssum[i];
    float inv = 1.0f / tot;

    a.x *= inv; a.y *= inv; a.z *= inv; a.w *= inv;
    b.x *= inv; b.y *= inv; b.z *= inv; b.w *= inv;
    *reinterpret_cast<float4*>(p + tid * 4) = a;
    *reinterpret_cast<float4*>(p + 1024 + tid * 4) = b;
}

// ---------------------------------------------------------------------------
// Kernel C: out[t,h,d] = sum_s W[h,t,s] * V[s,h,d]
// 128(t) x 64(d) tile per block, BK=32 chunks, double-buffered SMEM with
// register staging. Per thread: 4(t) x 8(d) register tile.
// ---------------------------------------------------------------------------
#define PV_BUF_FLOATS (32 * 132 + 32 * 68)   // sWT + sV per buffer

__global__ __launch_bounds__(256, 2) void pv_kernel(
    const float* __restrict__ W, const float* __restrict__ V,
    float* __restrict__ Out)
{
    extern __shared__ float sm[];
    const int h   = blockIdx.y;
    const int tb  = blockIdx.x * 128;
    const int tid = threadIdx.x;
    const int tg  = tid >> 3;   // 0..31 -> 4 t-rows each
    const int dg  = tid & 7;    // 0..7  -> d cols {dg*4..+3, dg*4+32..+3}
    const int d0  = dg * 4, d1 = d0 + 32;

    float4 wreg[4];
    float4 vreg[2];

    auto loadg = [&](int kc) {
#pragma unroll
        for (int k = 0; k < 4; ++k) {
            int i  = tid + k * 256;
            int tr = i >> 3;
            int s4 = (i & 7) << 2;
            wreg[k] = *reinterpret_cast<const float4*>(
                W + ((size_t)h * TGT + tb + tr) * SRC + kc * 32 + s4);
        }
#pragma unroll
        for (int k = 0; k < 2; ++k) {
            int i  = tid + k * 256;
            int sr = i >> 4;
            int d4 = (i & 15) << 2;
            vreg[k] = *reinterpret_cast<const float4*>(
                V + (size_t)(kc * 32 + sr) * (BHN * DH) + h * DH + d4);
        }
    };

    auto stores = [&](int b) {
        float* sWT = sm + b * PV_BUF_FLOATS;            // [32][132] s-major
        float* sV  = sWT + 32 * 132;                    // [32][68]
#pragma unroll
        for (int k = 0; k < 4; ++k) {
            int i  = tid + k * 256;
            int tr = i >> 3;
            int s4 = (i & 7) << 2;
            sWT[(s4 + 0) * 132 + tr] = wreg[k].x;
            sWT[(s4 + 1) * 132 + tr] = wreg[k].y;
            sWT[(s4 + 2) * 132 + tr] = wreg[k].z;
            sWT[(s4 + 3) * 132 + tr] = wreg[k].w;
        }
#pragma unroll
        for (int k = 0; k < 2; ++k) {
            int i  = tid + k * 256;
            int sr = i >> 4;
            int d4 = (i & 15) << 2;
            *reinterpret_cast<float4*>(&sV[sr * 68 + d4]) = vreg[k];
        }
    };

    float acc[4][8];
#pragma unroll
    for (int i = 0; i < 4; ++i)
#pragma unroll
        for (int j = 0; j < 8; ++j) acc[i][j] = 0.0f;

    loadg(0);
    stores(0);
    __syncthreads();

    for (int kc = 0; kc < 64; ++kc) {
        if (kc < 63) loadg(kc + 1);

        const float* sWT = sm + (kc & 1) * PV_BUF_FLOATS;
        const float* sV  = sWT + 32 * 132;
#pragma unroll 4
        for (int s = 0; s < 32; ++s) {
            float4 wv = *reinterpret_cast<const float4*>(&sWT[s * 132 + tg * 4]);
            float4 va = *reinterpret_cast<const float4*>(&sV[s * 68 + d0]);
            float4 vb = *reinterpret_cast<const float4*>(&sV[s * 68 + d1]);
            float ws[4] = {wv.x, wv.y, wv.z, wv.w};
            float vs[8] = {va.x, va.y, va.z, va.w, vb.x, vb.y, vb.z, vb.w};
#pragma unroll
            for (int i = 0; i < 4; ++i)
#pragma unroll
                for (int j = 0; j < 8; ++j) acc[i][j] += ws[i] * vs[j];
        }

        if (kc < 63) stores((kc + 1) & 1);
        __syncthreads();
    }

#pragma unroll
    for (int i = 0; i < 4; ++i) {
        int t = tb + tg * 4 + i;
        float* o = Out + (size_t)t * (BHN * DH) + h * DH;
        float4 oa = make_float4(acc[i][0], acc[i][1], acc[i][2], acc[i][3]);
        float4 ob = make_float4(acc[i][4], acc[i][5], acc[i][6], acc[i][7]);
        *reinterpret_cast<float4*>(o + d0) = oa;
        *reinterpret_cast<float4*>(o + d1) = ob;
    }
}

// ---------------------------------------------------------------------------
// Launch: out buffer = [out (2048*16*64) | w (16*2048*2048)] fp32.
// ---------------------------------------------------------------------------
extern "C" void kernel_launch(void* const* d_in, const int* in_sizes, int n_in,
                              void* d_out, int out_size)
{
    const float* Q = (const float*)d_in[0];
    const float* K = (const float*)d_in[1];
    const float* V = (const float*)d_in[2];
    const int*   M = (const int*)d_in[3];

    float* out = (float*)d_out;
    float* W   = out + (size_t)TGT * BHN * DH;   // w region after out region

    const int qk_smem = 2 * 64 * 132 * (int)sizeof(float);          // 67584 B
    const int pv_smem = 2 * PV_BUF_FLOATS * (int)sizeof(float);     // 51200 B
    cudaFuncSetAttribute(qk_logits_kernel,
                         cudaFuncAttributeMaxDynamicSharedMemorySize, qk_smem);
    cudaFuncSetAttribute(pv_kernel,
                         cudaFuncAttributeMaxDynamicSharedMemorySize, pv_smem);

    qk_logits_kernel<<<dim3(SRC / 128, TGT / 128, BHN), 256, qk_smem>>>(Q, K, M, W);
    softmax_kernel<<<BHN * TGT, 256>>>(W);
    pv_kernel<<<dim3(TGT / 128, BHN), 256, pv_smem>>>(W, V, out);
}

// round 7
// speedup vs baseline: 2.4678x; 2.4678x over previous
#include <cuda_runtime.h>
#include <cuda_bf16.h>
#include <cstdint>

#define TGT 2048
#define SRC 2048
#define BHN 16
#define DH  64
#define QK_SCALE 0.125f

#define STR 72   // bf16 halfs per SMEM row (144 B): conflict-free ldmatrix, 16B-aligned

// ---------------------------------------------------------------------------
// Helpers
// ---------------------------------------------------------------------------
__device__ __forceinline__ uint32_t smem_to_u32(const void* p) {
    uint32_t a;
    asm("{ .reg .u64 t; cvta.to.shared.u64 t, %1; cvt.u32.u64 %0, t; }"
        : "=r"(a) : "l"(p));
    return a;
}

__device__ __forceinline__ void ldmx4(uint32_t* r, uint32_t a) {
    asm volatile("ldmatrix.sync.aligned.m8n8.x4.shared.b16 {%0,%1,%2,%3}, [%4];"
                 : "=r"(r[0]), "=r"(r[1]), "=r"(r[2]), "=r"(r[3]) : "r"(a));
}

__device__ __forceinline__ void mma_bf16(float* c, const uint32_t* a, const uint32_t* b) {
    asm volatile(
        "mma.sync.aligned.m16n8k16.row.col.f32.bf16.bf16.f32 "
        "{%0,%1,%2,%3}, {%4,%5,%6,%7}, {%8,%9}, {%0,%1,%2,%3};"
        : "+f"(c[0]), "+f"(c[1]), "+f"(c[2]), "+f"(c[3])
        : "r"(a[0]), "r"(a[1]), "r"(a[2]), "r"(a[3]), "r"(b[0]), "r"(b[1]));
}

__device__ __forceinline__ uint32_t pack_hi(float a, float b) {
    __nv_bfloat162 t = __floats2bfloat162_rn(a, b);
    return *reinterpret_cast<uint32_t*>(&t);
}
__device__ __forceinline__ float bf_hi(float x) {
    return __bfloat162float(__float2bfloat16_rn(x));
}
__device__ __forceinline__ uint32_t pack_lo(float a, float b) {
    __nv_bfloat162 t = __floats2bfloat162_rn(a - bf_hi(a), b - bf_hi(b));
    return *reinterpret_cast<uint32_t*>(&t);
}

// ---------------------------------------------------------------------------
// Kernel A: W[h,t,s] = mask ? -1e8 : (Q/8)·K   (bf16-split HMMA)
// Block 256 thr, tile 128x128. Warps 2(t) x 4(s); warp tile 64x32.
// ---------------------------------------------------------------------------
#define QK_SMEM_BYTES (4 * 128 * STR * 2)   // Qhi, Qlo, Khi, Klo

__global__ __launch_bounds__(256) void qk_tc_kernel(
    const float* __restrict__ Q, const float* __restrict__ K,
    const int* __restrict__ mask, float* __restrict__ W)
{
    extern __shared__ char smem[];
    __nv_bfloat16* sQh = reinterpret_cast<__nv_bfloat16*>(smem);
    __nv_bfloat16* sQl = sQh + 128 * STR;
    __nv_bfloat16* sKh = sQl + 128 * STR;
    __nv_bfloat16* sKl = sKh + 128 * STR;

    const int tid = threadIdx.x;
    const int h  = blockIdx.z;
    const int tb = blockIdx.y * 128;
    const int sb = blockIdx.x * 128;

    // Convert Q (scaled) and K tiles to bf16 hi/lo.
#pragma unroll
    for (int k = 0; k < 8; ++k) {
        int i  = tid + k * 256;       // float4 index 0..2047
        int r  = i >> 4;
        int c4 = (i & 15) << 2;
        int hidx = r * STR + c4;

        float4 q = *reinterpret_cast<const float4*>(
            Q + (size_t)(tb + r) * (BHN * DH) + h * DH + c4);
        q.x *= QK_SCALE; q.y *= QK_SCALE; q.z *= QK_SCALE; q.w *= QK_SCALE;
        uint32_t* dh = reinterpret_cast<uint32_t*>(sQh + hidx);
        uint32_t* dl = reinterpret_cast<uint32_t*>(sQl + hidx);
        dh[0] = pack_hi(q.x, q.y); dh[1] = pack_hi(q.z, q.w);
        dl[0] = pack_lo(q.x, q.y); dl[1] = pack_lo(q.z, q.w);

        float4 kk = *reinterpret_cast<const float4*>(
            K + (size_t)(sb + r) * (BHN * DH) + h * DH + c4);
        uint32_t* eh = reinterpret_cast<uint32_t*>(sKh + hidx);
        uint32_t* el = reinterpret_cast<uint32_t*>(sKl + hidx);
        eh[0] = pack_hi(kk.x, kk.y); eh[1] = pack_hi(kk.z, kk.w);
        el[0] = pack_lo(kk.x, kk.y); el[1] = pack_lo(kk.z, kk.w);
    }
    __syncthreads();

    const int lane = tid & 31, wid = tid >> 5;
    const int wt = (wid >> 2) * 64;   // warp t offset in tile
    const int ws = (wid & 3) * 32;    // warp s offset in tile

    const uint32_t bQh = smem_to_u32(sQh), bQl = smem_to_u32(sQl);
    const uint32_t bKh = smem_to_u32(sKh), bKl = smem_to_u32(sKl);

    // ldmatrix address components
    const int a_row = (lane & 15);               // + wt + mi*16
    const int a_co8 = (lane >> 4) << 3;          // k +8 for lanes 16-31
    const int b_row = (lane & 7) + ((lane & 16) >> 1);  // + ws + p*16
    const int b_co8 = (lane & 8);                // k +8 for lanes 8-15/24-31

    float acc[4][4][4];
#pragma unroll
    for (int i = 0; i < 4; ++i)
#pragma unroll
        for (int j = 0; j < 4; ++j)
#pragma unroll
            for (int q = 0; q < 4; ++q) acc[i][j][q] = 0.0f;

#pragma unroll
    for (int ks = 0; ks < 4; ++ks) {
        const int k0 = ks * 16;
        uint32_t ah[4][4], al[4][4], bh[2][4], bl[2][4];
#pragma unroll
        for (int mi = 0; mi < 4; ++mi) {
            uint32_t off = ((wt + mi * 16 + a_row) * STR + k0 + a_co8) * 2;
            ldmx4(ah[mi], bQh + off);
            ldmx4(al[mi], bQl + off);
        }
#pragma unroll
        for (int p = 0; p < 2; ++p) {
            uint32_t off = ((ws + p * 16 + b_row) * STR + k0 + b_co8) * 2;
            ldmx4(bh[p], bKh + off);
            ldmx4(bl[p], bKl + off);
        }
#pragma unroll
        for (int mi = 0; mi < 4; ++mi)
#pragma unroll
            for (int ni = 0; ni < 4; ++ni) {
                const uint32_t* Bh = &bh[ni >> 1][(ni & 1) * 2];
                const uint32_t* Bl = &bl[ni >> 1][(ni & 1) * 2];
                mma_bf16(acc[mi][ni], ah[mi], Bh);
                mma_bf16(acc[mi][ni], ah[mi], Bl);
                mma_bf16(acc[mi][ni], al[mi], Bh);
            }
    }

    // Epilogue: mask + store (float2 per fragment row, sector-coalesced).
#pragma unroll
    for (int mi = 0; mi < 4; ++mi) {
#pragma unroll
        for (int ni = 0; ni < 4; ++ni) {
            int t0 = tb + wt + mi * 16 + (lane >> 2);
            int s  = sb + ws + ni * 8 + (lane & 3) * 2;

            int2 m0 = *reinterpret_cast<const int2*>(mask + (size_t)t0 * SRC + s);
            float2 o0;
            o0.x = m0.x ? -1e8f : acc[mi][ni][0];
            o0.y = m0.y ? -1e8f : acc[mi][ni][1];
            *reinterpret_cast<float2*>(W + ((size_t)h * TGT + t0) * SRC + s) = o0;

            int t1 = t0 + 8;
            int2 m1 = *reinterpret_cast<const int2*>(mask + (size_t)t1 * SRC + s);
            float2 o1;
            o1.x = m1.x ? -1e8f : acc[mi][ni][2];
            o1.y = m1.y ? -1e8f : acc[mi][ni][3];
            *reinterpret_cast<float2*>(W + ((size_t)h * TGT + t1) * SRC + s) = o1;
        }
    }
}

// ---------------------------------------------------------------------------
// Kernel B: in-place row softmax over W (unchanged, known good).
// ---------------------------------------------------------------------------
__global__ __launch_bounds__(256) void softmax_kernel(float* __restrict__ W)
{
    __shared__ float smax[8];
    __shared__ float ssum[8];

    float* p = W + (size_t)blockIdx.x * SRC;
    const int tid = threadIdx.x;

    float4 a = *reinterpret_cast<const float4*>(p + tid * 4);
    float4 b = *reinterpret_cast<const float4*>(p + 1024 + tid * 4);

    float m = fmaxf(fmaxf(fmaxf(a.x, a.y), fmaxf(a.z, a.w)),
                    fmaxf(fmaxf(b.x, b.y), fmaxf(b.z, b.w)));
#pragma unroll
    for (int o = 16; o > 0; o >>= 1) m = fmaxf(m, __shfl_xor_sync(0xffffffffu, m, o));
    if ((tid & 31) == 0) smax[tid >> 5] = m;
    __syncthreads();
    float mx = smax[0];
#pragma unroll
    for (int i = 1; i < 8; ++i) mx = fmaxf(mx, smax[i]);

    a.x = __expf(a.x - mx); a.y = __expf(a.y - mx);
    a.z = __expf(a.z - mx); a.w = __expf(a.w - mx);
    b.x = __expf(b.x - mx); b.y = __expf(b.y - mx);
    b.z = __expf(b.z - mx); b.w = __expf(b.w - mx);

    float s = a.x + a.y + a.z + a.w + b.x + b.y + b.z + b.w;
#pragma unroll
    for (int o = 16; o > 0; o >>= 1) s += __shfl_xor_sync(0xffffffffu, s, o);
    if ((tid & 31) == 0) ssum[tid >> 5] = s;
    __syncthreads();
    float tot = 0.0f;
#pragma unroll
    for (int i = 0; i < 8; ++i) tot += ssum[i];
    float inv = 1.0f / tot;

    a.x *= inv; a.y *= inv; a.z *= inv; a.w *= inv;
    b.x *= inv; b.y *= inv; b.z *= inv; b.w *= inv;
    *reinterpret_cast<float4*>(p + tid * 4) = a;
    *reinterpret_cast<float4*>(p + 1024 + tid * 4) = b;
}

// ---------------------------------------------------------------------------
// Kernel C: out[t,h,d] = sum_s W[h,t,s] * V[s,h,d]   (bf16-split HMMA)
// Block 256 thr, tile 128t x 64d; 32 s-chunks of 64; register accumulate.
// Warps 2(t) x 4(d); warp tile 64t x 16d.
// ---------------------------------------------------------------------------
#define PV_SMEM_BYTES ((2 * 128 * STR + 2 * 64 * STR) * 2)   // Phi,Plo,Vhi,Vlo

__global__ __launch_bounds__(256) void pv_tc_kernel(
    const float* __restrict__ W, const float* __restrict__ V,
    float* __restrict__ Out)
{
    extern __shared__ char smem[];
    __nv_bfloat16* sPh = reinterpret_cast<__nv_bfloat16*>(smem);
    __nv_bfloat16* sPl = sPh + 128 * STR;
    __nv_bfloat16* sVh = sPl + 128 * STR;
    __nv_bfloat16* sVl = sVh + 64 * STR;

    const int tid = threadIdx.x;
    const int lane = tid & 31, wid = tid >> 5;
    const int h  = blockIdx.y;
    const int tb = blockIdx.x * 128;
    const int wt = (wid >> 2) * 64;
    const int wd = (wid & 3) * 16;

    const uint32_t bPh = smem_to_u32(sPh), bPl = smem_to_u32(sPl);
    const uint32_t bVh = smem_to_u32(sVh), bVl = smem_to_u32(sVl);

    const int a_row = (lane & 15);
    const int a_co8 = (lane >> 4) << 3;
    const int b_row = (lane & 7) + ((lane & 16) >> 1);
    const int b_co8 = (lane & 8);

    float acc[4][2][4];
#pragma unroll
    for (int i = 0; i < 4; ++i)
#pragma unroll
        for (int j = 0; j < 2; ++j)
#pragma unroll
            for (int q = 0; q < 4; ++q) acc[i][j][q] = 0.0f;

#pragma unroll 1
    for (int c = 0; c < 32; ++c) {
        const int s0 = c * 64;

        // P chunk [128 t][64 s] -> bf16 hi/lo.
#pragma unroll
        for (int k = 0; k < 8; ++k) {
            int i  = tid + k * 256;
            int r  = i >> 4;
            int c4 = (i & 15) << 2;
            int hidx = r * STR + c4;
            float4 p = *reinterpret_cast<const float4*>(
                W + ((size_t)h * TGT + tb + r) * SRC + s0 + c4);
            uint32_t* dh = reinterpret_cast<uint32_t*>(sPh + hidx);
            uint32_t* dl = reinterpret_cast<uint32_t*>(sPl + hidx);
            dh[0] = pack_hi(p.x, p.y); dh[1] = pack_hi(p.z, p.w);
            dl[0] = pack_lo(p.x, p.y); dl[1] = pack_lo(p.z, p.w);
        }

        // V chunk transposed: sV[d][s] (rows d, contiguous s).
#pragma unroll
        for (int k = 0; k < 2; ++k) {
            int u  = tid + k * 256;       // 0..511
            int s2 = u & 31;              // s-pair index
            int d4 = (u >> 5) << 2;       // 0..60
            float4 A = *reinterpret_cast<const float4*>(
                V + (size_t)(s0 + s2 * 2) * (BHN * DH) + h * DH + d4);
            float4 B = *reinterpret_cast<const float4*>(
                V + (size_t)(s0 + s2 * 2 + 1) * (BHN * DH) + h * DH + d4);
            float av[4] = {A.x, A.y, A.z, A.w};
            float bv[4] = {B.x, B.y, B.z, B.w};
#pragma unroll
            for (int j = 0; j < 4; ++j) {
                int idx = (d4 + j) * STR + s2 * 2;
                *reinterpret_cast<uint32_t*>(sVh + idx) = pack_hi(av[j], bv[j]);
                *reinterpret_cast<uint32_t*>(sVl + idx) = pack_lo(av[j], bv[j]);
            }
        }
        __syncthreads();

#pragma unroll
        for (int ks = 0; ks < 4; ++ks) {
            const int k0 = ks * 16;
            uint32_t ah[4][4], al[4][4], bh[4], bl[4];
            uint32_t offB = ((wd + b_row) * STR + k0 + b_co8) * 2;
            ldmx4(bh, bVh + offB);
            ldmx4(bl, bVl + offB);
#pragma unroll
            for (int mi = 0; mi < 4; ++mi) {
                uint32_t off = ((wt + mi * 16 + a_row) * STR + k0 + a_co8) * 2;
                ldmx4(ah[mi], bPh + off);
                ldmx4(al[mi], bPl + off);
            }
#pragma unroll
            for (int mi = 0; mi < 4; ++mi)
#pragma unroll
                for (int ni = 0; ni < 2; ++ni) {
                    mma_bf16(acc[mi][ni], ah[mi], &bh[ni * 2]);
                    mma_bf16(acc[mi][ni], ah[mi], &bl[ni * 2]);
                    mma_bf16(acc[mi][ni], al[mi], &bh[ni * 2]);
                }
        }
        __syncthreads();
    }

    // Epilogue: Out[t, h, d].
#pragma unroll
    for (int mi = 0; mi < 4; ++mi) {
#pragma unroll
        for (int ni = 0; ni < 2; ++ni) {
            int t0 = tb + wt + mi * 16 + (lane >> 2);
            int d  = wd + ni * 8 + (lane & 3) * 2;
            float2 o0 = make_float2(acc[mi][ni][0], acc[mi][ni][1]);
            float2 o1 = make_float2(acc[mi][ni][2], acc[mi][ni][3]);
            *reinterpret_cast<float2*>(Out + (size_t)t0 * (BHN * DH) + h * DH + d) = o0;
            *reinterpret_cast<float2*>(Out + (size_t)(t0 + 8) * (BHN * DH) + h * DH + d) = o1;
        }
    }
}

// ---------------------------------------------------------------------------
// Launch: out buffer = [out (2048*16*64) | w (16*2048*2048)] fp32.
// ---------------------------------------------------------------------------
extern "C" void kernel_launch(void* const* d_in, const int* in_sizes, int n_in,
                              void* d_out, int out_size)
{
    const float* Q = (const float*)d_in[0];
    const float* K = (const float*)d_in[1];
    const float* V = (const float*)d_in[2];
    const int*   M = (const int*)d_in[3];

    float* out = (float*)d_out;
    float* W   = out + (size_t)TGT * BHN * DH;

    cudaFuncSetAttribute(qk_tc_kernel,
                         cudaFuncAttributeMaxDynamicSharedMemorySize, QK_SMEM_BYTES);
    cudaFuncSetAttribute(pv_tc_kernel,
                         cudaFuncAttributeMaxDynamicSharedMemorySize, PV_SMEM_BYTES);

    qk_tc_kernel<<<dim3(SRC / 128, TGT / 128, BHN), 256, QK_SMEM_BYTES>>>(Q, K, M, W);
    softmax_kernel<<<BHN * TGT, 256>>>(W);
    pv_tc_kernel<<<dim3(TGT / 128, BHN), 256, PV_SMEM_BYTES>>>(W, V, out);
}